// round 12
// baseline (speedup 1.0000x reference)
#include <cuda_runtime.h>
#include <cuda_bf16.h>

// x: (256,64,25,3) f32; W_conv: (3,192) f32; W_a: (128,1) f32; out: (256,3,25,25) f32
// Verified math (R1/R3/R7):
//   xbar[j] = sum_t x[n,t,j], j=v*3+i (1/64 folded into u)
//   u{1,2}[i,k] = (1/64) sum_c W_conv[i,c*3+k]*W_a[{0,64}+c]
//   s{1,2}[v,k] = sum_i xbar[v*3+i]*u{1,2}[i,k]
//   row(0..74), col q: e = s1[(row%3)*25+q] + s2[(row/3)*3 + ((row%3)+q)%3]
//   exp(leaky(e)) = max(E1[r]*E2[c], F1[r]*F2[c]), E=exp2(L2E*s), F=exp2(0.2*L2E*s)
// R12 = R9 (best measured: 300x4 loaders, dedicated u warps) + interleaved-q
//   phase 3 (lane part handles q = part+4j): lanes of a row write 4 consecutive
//   floats per STG (~3x fewer store sectors); k still rotates +1/step (4≡1 mod 3).

#define TPB 448

__device__ __forceinline__ unsigned long long add2(unsigned long long a, unsigned long long b) {
    unsigned long long r;
    asm("add.rn.f32x2 %0, %1, %2;" : "=l"(r) : "l"(a), "l"(b));
    return r;
}
__device__ __forceinline__ unsigned long long mul2(unsigned long long a, unsigned long long b) {
    unsigned long long r;
    asm("mul.rn.f32x2 %0, %1, %2;" : "=l"(r) : "l"(a), "l"(b));
    return r;
}
__device__ __forceinline__ unsigned long long pack2(float lo, float hi) {
    unsigned long long r;
    asm("mov.b64 %0, {%1, %2};" : "=l"(r) : "f"(lo), "f"(hi));
    return r;
}
__device__ __forceinline__ void unpack2(unsigned long long v, float &lo, float &hi) {
    asm("mov.b64 {%0, %1}, %2;" : "=f"(lo), "=f"(hi) : "l"(v));
}
__device__ __forceinline__ float ex2a(float x) {
    float r; asm("ex2.approx.f32 %0, %1;" : "=f"(r) : "f"(x)); return r;
}

__global__ __launch_bounds__(TPB)
void gat_adj_kernel(const float* __restrict__ x,
                    const float* __restrict__ Wc,
                    const float* __restrict__ Wa,
                    float* __restrict__ out)
{
    __shared__ __align__(16) float buf[1200];           // 16 partial slots x 75 cols
    __shared__ float uu[18];                            // [which*9+i*3+k], /64 folded
    __shared__ unsigned long long ep1[75], ep2[75];     // packed (E,F) per column

    const int n   = blockIdx.x;
    const int tid = threadIdx.x;

    if (tid < 300) {
        // ---- Loader warps: pure x path. 4 LDG.128 at t=0, f32x2 fold, STS.128 ----
        const ulonglong2* xg = reinterpret_cast<const ulonglong2*>(x) + (size_t)n * 1200;
        ulonglong2 xa = xg[tid];
        ulonglong2 xb = xg[tid + 300];
        ulonglong2 xc = xg[tid + 600];
        ulonglong2 xd = xg[tid + 900];
        ulonglong2 s;
        s.x = add2(add2(xa.x, xb.x), add2(xc.x, xd.x));
        s.y = add2(add2(xa.y, xb.y), add2(xc.y, xd.y));
        reinterpret_cast<ulonglong2*>(buf)[tid] = s;   // buf[slot*75+col], col=(4tid+m)%75
    } else if (tid >= 304) {
        // ---- u warps: 18 outputs x 8 lanes x 8 terms, overlapped with x latency ----
        const int idx = tid - 304;                      // 0..143
        const int o = idx >> 3;                         // 0..17
        const int p = idx & 7;
        const int which = o / 9;
        const int rem   = o % 9;
        const int i     = rem / 3;
        const int k     = rem % 3;
        const int c0    = p * 8;
        const float* wcb = Wc + i * 192 + k;
        const float4 wa0 = *reinterpret_cast<const float4*>(Wa + which * 64 + c0);
        const float4 wa1 = *reinterpret_cast<const float4*>(Wa + which * 64 + c0 + 4);
        float acc = wcb[(c0 + 0) * 3] * wa0.x + wcb[(c0 + 1) * 3] * wa0.y
                  + wcb[(c0 + 2) * 3] * wa0.z + wcb[(c0 + 3) * 3] * wa0.w
                  + wcb[(c0 + 4) * 3] * wa1.x + wcb[(c0 + 5) * 3] * wa1.y
                  + wcb[(c0 + 6) * 3] * wa1.z + wcb[(c0 + 7) * 3] * wa1.w;
        // warp 9 executes with lanes 16-31 only; warps 10-13 with all lanes.
        const unsigned mask = (tid < 320) ? 0xFFFF0000u : 0xFFFFFFFFu;
        acc += __shfl_xor_sync(mask, acc, 1);
        acc += __shfl_xor_sync(mask, acc, 2);
        acc += __shfl_xor_sync(mask, acc, 4);
        if (p == 0) uu[o] = acc * (1.0f / 64.0f);
    }
    __syncthreads();   // bar 0

    // ---- Phase 2: fold + scores + exps; 3 warps, col = w*27+lane ----
    if (tid < 96) {
        const int w    = tid >> 5;
        const int lane = tid & 31;
        const int col  = w * 27 + lane;
        const bool on  = (lane < 27) && (col < 75);
        const int colc = on ? col : 74;

        float xv = 0.f;
        #pragma unroll
        for (int i = 0; i < 16; i++) xv += buf[i * 75 + colc];

        const int k    = lane % 3;                     // == col%3 when on
        const int base = lane - k;
        const float a0 = __shfl_sync(0xffffffffu, xv, base);
        const float a1 = __shfl_sync(0xffffffffu, xv, base + 1);
        const float a2 = __shfl_sync(0xffffffffu, xv, base + 2);

        const float s1 = a0 * uu[k]     + a1 * uu[3 + k]  + a2 * uu[6 + k];
        const float s2 = a0 * uu[9 + k] + a1 * uu[12 + k] + a2 * uu[15 + k];
        const float L2E  = 1.4426950408889634f;
        const float L2E5 = 0.2f * L2E;
        const float E1 = ex2a(s1 * L2E),  F1 = ex2a(s1 * L2E5);
        const float E2 = ex2a(s2 * L2E),  F2 = ex2a(s2 * L2E5);
        if (on) {
            ep1[col] = pack2(E1, F1);
            ep2[col] = pack2(E2, F2);
        }
    }
    __syncthreads();   // bar 1

    // ---- Phase 3: softmax, 4 threads/row, interleaved q = part + 4j ----
    {
        int row = tid >> 2;
        const bool act = (row < 75);
        if (row > 74) row = 74;                 // tid 300..447: safe duplicate work
        const int part = tid & 3;
        const int d  = row % 3;
        const int a3 = row - d;
        const int r0 = d * 25 + part;

        const unsigned long long c0 = ep2[a3];
        const unsigned long long c1 = ep2[a3 + 1];
        const unsigned long long c2 = ep2[a3 + 2];

        const int cnt = (part == 0) ? 7 : 6;    // q = part,part+4,... < 25

        // k for step j: (d + part + 4j) % 3 = (d + part + j) % 3 -> rotate +1/step
        const int kk0 = (d + part) % 3;
        unsigned long long ra = (kk0 == 0) ? c0 : ((kk0 == 1) ? c1 : c2);
        unsigned long long rb = (kk0 == 0) ? c1 : ((kk0 == 1) ? c2 : c0);
        unsigned long long rc = (kk0 == 0) ? c2 : ((kk0 == 1) ? c0 : c1);

        float vals[7];
        float sum0 = 0.f, sum1 = 0.f;
        #pragma unroll
        for (int j = 0; j < 7; j++) {
            if (j < cnt) {
                const unsigned long long pr = mul2(ep1[r0 + 4 * j], ra);
                float pe, pf;
                unpack2(pr, pe, pf);
                const float vl = fmaxf(pe, pf);   // exp2(leaky(e)) by monotonicity
                vals[j] = vl;
                if (j & 1) sum1 += vl; else sum0 += vl;
                unsigned long long t = ra; ra = rb; rb = rc; rc = t;
            }
        }
        float sum = sum0 + sum1;
        sum += __shfl_xor_sync(0xffffffffu, sum, 1);
        sum += __shfl_xor_sync(0xffffffffu, sum, 2);
        const float inv = __fdividef(1.0f, sum);

        if (act) {
            float* og = out + (size_t)n * 1875 + row * 25 + part;
            #pragma unroll
            for (int j = 0; j < 7; j++)
                if (j < cnt) og[4 * j] = vals[j] * inv;   // lanes 0-3: 16B contiguous runs
        }
    }
}

extern "C" void kernel_launch(void* const* d_in, const int* in_sizes, int n_in,
                              void* d_out, int out_size)
{
    const float* x  = (const float*)d_in[0];
    const float* Wc = (const float*)d_in[1];
    const float* Wa = (const float*)d_in[2];
    float* out = (float*)d_out;
    gat_adj_kernel<<<256, TPB>>>(x, Wc, Wa, out);
}

// round 13
// speedup vs baseline: 1.0257x; 1.0257x over previous
#include <cuda_runtime.h>
#include <cuda_bf16.h>

// x: (256,64,25,3) f32; W_conv: (3,192) f32; W_a: (128,1) f32; out: (256,3,25,25) f32
// Verified math (R1/R3/R7/R11/R12):
//   xbar[j] = sum_t x[n,t,j], j=v*3+i (1/64 folded into u)
//   u{1,2}[i,k] = (1/64) sum_c W_conv[i,c*3+k]*W_a[{0,64}+c]
//   s{1,2}[v,k] = sum_i xbar[v*3+i]*u{1,2}[i,k]
//   row(0..74), col q: e = s1[(row%3)*25+q] + s2[(row/3)*3 + ((row%3)+q)%3]
//   exp(leaky(e)) = max(E1[r]*E2[c], F1[r]*F2[c]), E=exp2(L2E*s), F=exp2(0.2*L2E*s)
// R13 = R12 + in-warp s-fold: loaders re-indexed (j=tid>>2, s=tid&3, float4 ids
//   j+75s+300k) so the 4 same-column-quad threads are ADJACENT LANES; two 64-bit
//   shfl_xor levels fold s in-warp. Smem partials 1200->300; phase 2 = R11's
//   verified 12-LDS direct fold (buf[c]+buf[c+75]+buf[c+150]+buf[c+225]).

#define TPB 448

__device__ __forceinline__ unsigned long long add2(unsigned long long a, unsigned long long b) {
    unsigned long long r;
    asm("add.rn.f32x2 %0, %1, %2;" : "=l"(r) : "l"(a), "l"(b));
    return r;
}
__device__ __forceinline__ unsigned long long mul2(unsigned long long a, unsigned long long b) {
    unsigned long long r;
    asm("mul.rn.f32x2 %0, %1, %2;" : "=l"(r) : "l"(a), "l"(b));
    return r;
}
__device__ __forceinline__ unsigned long long pack2(float lo, float hi) {
    unsigned long long r;
    asm("mov.b64 %0, {%1, %2};" : "=l"(r) : "f"(lo), "f"(hi));
    return r;
}
__device__ __forceinline__ void unpack2(unsigned long long v, float &lo, float &hi) {
    asm("mov.b64 {%0, %1}, %2;" : "=f"(lo), "=f"(hi) : "l"(v));
}
__device__ __forceinline__ float ex2a(float x) {
    float r; asm("ex2.approx.f32 %0, %1;" : "=f"(r) : "f"(x)); return r;
}

__global__ __launch_bounds__(TPB)
void gat_adj_kernel(const float* __restrict__ x,
                    const float* __restrict__ Wc,
                    const float* __restrict__ Wa,
                    float* __restrict__ out)
{
    __shared__ __align__(16) float buf[304];            // 4 groups x 75 cols (buf[i]: col i%75, group i/75)
    __shared__ float uu[18];                            // [which*9+i*3+k], /64 folded
    __shared__ unsigned long long ep1[75], ep2[75];     // packed (E,F) per column

    const int n   = blockIdx.x;
    const int tid = threadIdx.x;

    if (tid < 300) {
        // ---- Loaders: j = tid>>2 (0..74), s = tid&3. float4 ids j+75s+300k. ----
        // Columns of this thread's quad: (4j+m)%75, identical for all s,k.
        // Warp coalescing: each LDG.128 covers 4 runs of 8 consecutive float4s
        // (= 4 x 128B lines/warp, same as dense coalesced).
        const int j = tid >> 2;
        const int s = tid & 3;
        const ulonglong2* xg = reinterpret_cast<const ulonglong2*>(x)
                             + (size_t)n * 1200 + j + 75 * s;
        ulonglong2 v0 = xg[0];
        ulonglong2 v1 = xg[300];
        ulonglong2 v2 = xg[600];
        ulonglong2 v3 = xg[900];
        unsigned long long px = add2(add2(v0.x, v1.x), add2(v2.x, v3.x));
        unsigned long long py = add2(add2(v0.y, v1.y), add2(v2.y, v3.y));
        // s-fold across adjacent lanes (same j). Warp 9 has only lanes 0..11 here.
        const unsigned mask = (tid < 288) ? 0xFFFFFFFFu : 0x00000FFFu;
        px = add2(px, __shfl_xor_sync(mask, px, 1));
        py = add2(py, __shfl_xor_sync(mask, py, 1));
        px = add2(px, __shfl_xor_sync(mask, px, 2));
        py = add2(py, __shfl_xor_sync(mask, py, 2));
        if (s == 0) {
            ulonglong2 r; r.x = px; r.y = py;
            reinterpret_cast<ulonglong2*>(buf)[j] = r;   // buf[4j..4j+3]: 16-fold partial
        }
    } else if (tid >= 304) {
        // ---- u warps: 18 outputs x 8 lanes x 8 terms, overlapped with x latency ----
        const int idx = tid - 304;                      // 0..143
        const int o = idx >> 3;                         // 0..17
        const int p = idx & 7;
        const int which = o / 9;
        const int rem   = o % 9;
        const int i     = rem / 3;
        const int k     = rem % 3;
        const int c0    = p * 8;
        const float* wcb = Wc + i * 192 + k;
        const float4 wa0 = *reinterpret_cast<const float4*>(Wa + which * 64 + c0);
        const float4 wa1 = *reinterpret_cast<const float4*>(Wa + which * 64 + c0 + 4);
        float acc = wcb[(c0 + 0) * 3] * wa0.x + wcb[(c0 + 1) * 3] * wa0.y
                  + wcb[(c0 + 2) * 3] * wa0.z + wcb[(c0 + 3) * 3] * wa0.w
                  + wcb[(c0 + 4) * 3] * wa1.x + wcb[(c0 + 5) * 3] * wa1.y
                  + wcb[(c0 + 6) * 3] * wa1.z + wcb[(c0 + 7) * 3] * wa1.w;
        // warp 9 executes with lanes 16-31 only; warps 10-13 with all lanes.
        const unsigned mask = (tid < 320) ? 0xFFFF0000u : 0xFFFFFFFFu;
        acc += __shfl_xor_sync(mask, acc, 1);
        acc += __shfl_xor_sync(mask, acc, 2);
        acc += __shfl_xor_sync(mask, acc, 4);
        if (p == 0) uu[o] = acc * (1.0f / 64.0f);
    }
    __syncthreads();   // bar 0

    // ---- Phase 2: 75 threads, 12-LDS direct fold (verified R11), scores + exps ----
    if (tid < 75) {
        const int k  = tid % 3;
        const int v3 = tid - k;
        const float a0 = (buf[v3]     + buf[v3 + 75]) + (buf[v3 + 150] + buf[v3 + 225]);
        const float a1 = (buf[v3 + 1] + buf[v3 + 76]) + (buf[v3 + 151] + buf[v3 + 226]);
        const float a2 = (buf[v3 + 2] + buf[v3 + 77]) + (buf[v3 + 152] + buf[v3 + 227]);

        const float s1 = a0 * uu[k]     + a1 * uu[3 + k]  + a2 * uu[6 + k];
        const float s2 = a0 * uu[9 + k] + a1 * uu[12 + k] + a2 * uu[15 + k];
        const float L2E  = 1.4426950408889634f;
        const float L2E5 = 0.2f * L2E;
        const float E1 = ex2a(s1 * L2E),  F1 = ex2a(s1 * L2E5);
        const float E2 = ex2a(s2 * L2E),  F2 = ex2a(s2 * L2E5);
        ep1[tid] = pack2(E1, F1);
        ep2[tid] = pack2(E2, F2);
    }
    __syncthreads();   // bar 1

    // ---- Phase 3: softmax, 4 threads/row, interleaved q = part + 4j (R12) ----
    {
        int row = tid >> 2;
        const bool act = (row < 75);
        if (row > 74) row = 74;                 // tid 300..447: safe duplicate work
        const int part = tid & 3;
        const int d  = row % 3;
        const int a3 = row - d;
        const int r0 = d * 25 + part;

        const unsigned long long c0 = ep2[a3];
        const unsigned long long c1 = ep2[a3 + 1];
        const unsigned long long c2 = ep2[a3 + 2];

        const int cnt = (part == 0) ? 7 : 6;    // q = part,part+4,... < 25

        // k for step j: (d + part + 4j) % 3 = (d + part + j) % 3 -> rotate +1/step
        const int kk0 = (d + part) % 3;
        unsigned long long ra = (kk0 == 0) ? c0 : ((kk0 == 1) ? c1 : c2);
        unsigned long long rb = (kk0 == 0) ? c1 : ((kk0 == 1) ? c2 : c0);
        unsigned long long rc = (kk0 == 0) ? c2 : ((kk0 == 1) ? c0 : c1);

        float vals[7];
        float sum0 = 0.f, sum1 = 0.f;
        #pragma unroll
        for (int j = 0; j < 7; j++) {
            if (j < cnt) {
                const unsigned long long pr = mul2(ep1[r0 + 4 * j], ra);
                float pe, pf;
                unpack2(pr, pe, pf);
                const float vl = fmaxf(pe, pf);   // exp2(leaky(e)) by monotonicity
                vals[j] = vl;
                if (j & 1) sum1 += vl; else sum0 += vl;
                unsigned long long t = ra; ra = rb; rb = rc; rc = t;
            }
        }
        float sum = sum0 + sum1;
        sum += __shfl_xor_sync(0xffffffffu, sum, 1);
        sum += __shfl_xor_sync(0xffffffffu, sum, 2);
        const float inv = __fdividef(1.0f, sum);

        if (act) {
            float* og = out + (size_t)n * 1875 + row * 25 + part;
            #pragma unroll
            for (int j = 0; j < 7; j++)
                if (j < cnt) og[4 * j] = vals[j] * inv;   // lanes 0-3: 16B contiguous runs
        }
    }
}

extern "C" void kernel_launch(void* const* d_in, const int* in_sizes, int n_in,
                              void* d_out, int out_size)
{
    const float* x  = (const float*)d_in[0];
    const float* Wc = (const float*)d_in[1];
    const float* Wa = (const float*)d_in[2];
    float* out = (float*)d_out;
    gat_adj_kernel<<<256, TPB>>>(x, Wc, Wa, out);
}